// round 16
// baseline (speedup 1.0000x reference)
#include <cuda_runtime.h>
#include <cuda_fp16.h>
#include <cstdint>
#include <math.h>

// Problem dims
#define Bn   128
#define Tn   20
#define Vn   12000
#define En   512
#define Hn   512
#define VISn 512

// ===================== PTX helpers (sm_100 baseline) =====================
__device__ __forceinline__ uint32_t smem_u32(const void* p) {
    uint32_t a;
    asm("{ .reg .u64 t; cvta.to.shared.u64 t, %1; cvt.u32.u64 %0, t; }" : "=r"(a) : "l"(p));
    return a;
}
#define CP_ASYNC16(dst, src) \
    asm volatile("cp.async.cg.shared.global [%0], [%1], 16;" :: "r"(dst), "l"(src) : "memory")
#define CP_COMMIT() asm volatile("cp.async.commit_group;" ::: "memory")
#define CP_WAIT0()  asm volatile("cp.async.wait_group 0;" ::: "memory")
#define CP_WAIT2()  asm volatile("cp.async.wait_group 2;" ::: "memory")

__device__ __forceinline__ void ldsm4(uint32_t* r, uint32_t addr) {
    asm volatile("ldmatrix.sync.aligned.m8n8.x4.shared.b16 {%0,%1,%2,%3}, [%4];"
        : "=r"(r[0]), "=r"(r[1]), "=r"(r[2]), "=r"(r[3]) : "r"(addr));
}
__device__ __forceinline__ void mma16816(float* c, const uint32_t* a, const uint32_t* b) {
    asm volatile("mma.sync.aligned.m16n8k16.row.col.f32.f16.f16.f32 "
        "{%0,%1,%2,%3}, {%4,%5,%6,%7}, {%8,%9}, {%0,%1,%2,%3};"
        : "+f"(c[0]), "+f"(c[1]), "+f"(c[2]), "+f"(c[3])
        : "r"(a[0]), "r"(a[1]), "r"(a[2]), "r"(a[3]), "r"(b[0]), "r"(b[1]));
}

// ===================== scratch (device globals) =====================
__device__ float g_fv[Bn * 49 * VISn];
__device__ float g_features_all[Bn * 64 * VISn];
__device__ float g_att_fea[Bn * 64 * VISn];
__device__ float g_att_h[Bn * Tn * VISn];
__device__ float g_scores[Bn * (Tn - 1) * 64];
__device__ float g_xg[Bn * Tn * 4 * Hn];
__device__ float g_c[Bn * Hn];
__device__ float g_bias2[4 * Hn];
__device__ float g_part[8 * Bn * VISn];
__device__ unsigned g_bar;
__device__ int g_rowmap0[Bn];
__device__ int g_rowmapA[Bn * Tn];
__device__ int g_rowmapB[Bn * Tn];
__device__ int g_nk0;
__device__ int g_nkA;
__device__ int g_nkB;

// activations (single fp16, except hs which stays split for the recurrent path)
__device__ __half g_fT[Bn * 49 * VISn];
__device__ __half g_fall16[Bn * 64 * VISn];
__device__ __half g_we16[Bn * Tn * En];
__device__ __half g_x16[Bn * Tn * 1024];
__device__ __half g_hs_h[Bn * Tn * Hn], g_hs_l[Bn * Tn * Hn];
// weights: single fp16
__device__ __half g_wfc1[VISn * VISn];
__device__ __half g_wvw[VISn * VISn];
__device__ __half g_whw[VISn * En];
__device__ __half g_wih[4 * Hn * 1024];
__device__ __half g_wfc[Vn * Hn];
__device__ __half g_whh[4 * Hn * Hn];

__device__ __forceinline__ void split_write16(float v, __half* h, __half* l, long i) {
    __half hi = __float2half_rn(v);
    h[i] = hi;
    l[i] = __float2half_rn(v - __half2float(hi));
}

#define ROWB   80
#define ATILE  (64 * ROWB)           // 5120 B
#define BTILE  (128 * ROWB)          // 10240 B
#define B2TILE (256 * ROWB)          // 20480 B

// ===================== single-product GEMM: CTA 64x256, 2 CTAs/SM =====================
#define S2_STAGE (ATILE + B2TILE)        // 25600
#define S2_NSTG  4
#define S2_SMEM  (S2_NSTG * S2_STAGE)    // 102400

__global__ __launch_bounds__(256, 2)
void mma_gemm1(const __half* __restrict__ Ah, const __half* __restrict__ Bw,
               float* __restrict__ C, int ldc, const float* __restrict__ bias,
               int N, int K)
{
    extern __shared__ __align__(16) char smem[];
    const uint32_t sbase = smem_u32(smem);

    const int tid = threadIdx.x, wid = tid >> 5, lane = tid & 31;
    const int m0 = blockIdx.y * 64, n0 = blockIdx.x * 256;
    const int wm = wid & 1, wn = wid >> 1;

    const int NC = K >> 5;

    auto issue = [&](int c) {
        if (c < NC) {
            const long kc = (long)c * 32;
            const uint32_t sb = sbase + (c & (S2_NSTG - 1)) * S2_STAGE;
            {
                int row = tid >> 2, kq = tid & 3;
                CP_ASYNC16(sb + row * ROWB + kq * 16,
                           Ah + (long)(m0 + row) * K + kc + kq * 8);
            }
            #pragma unroll
            for (int i = 0; i < 4; i++) {
                int ch = tid + i * 256;
                int row = ch >> 2, kq = ch & 3;
                int gr = n0 + row;
                if (gr >= N) gr = N - 1;
                CP_ASYNC16(sb + ATILE + row * ROWB + kq * 16,
                           Bw + (long)gr * K + kc + kq * 8);
            }
        }
        CP_COMMIT();
    };

    float acc[2][8][4];
    #pragma unroll
    for (int mi = 0; mi < 2; mi++)
        #pragma unroll
        for (int ni = 0; ni < 8; ni++)
            #pragma unroll
            for (int q = 0; q < 4; q++) acc[mi][ni][q] = 0.f;

    const uint32_t a_off = (uint32_t)((wm * 32 + (lane & 15)) * ROWB + (lane >> 4) * 16);
    const uint32_t b_off = (uint32_t)((wn * 64 + ((lane >> 4) & 1) * 8 + (lane & 7)) * ROWB
                                      + ((lane >> 3) & 1) * 16);

    issue(0); issue(1); issue(2);

    for (int c = 0; c < NC; c++) {
        CP_WAIT2();
        __syncthreads();
        issue(c + 3);

        const uint32_t tb = sbase + (c & (S2_NSTG - 1)) * S2_STAGE;
        #pragma unroll
        for (int kk = 0; kk < 2; kk++) {
            const uint32_t kba = kk * 32;
            uint32_t ah[2][4], bb[8][2];
            #pragma unroll
            for (int mi = 0; mi < 2; mi++)
                ldsm4(ah[mi], tb + a_off + mi * 16 * ROWB + kba);
            #pragma unroll
            for (int nip = 0; nip < 4; nip++) {
                uint32_t t4[4];
                ldsm4(t4, tb + ATILE + b_off + nip * 16 * ROWB + kba);
                bb[2*nip][0] = t4[0]; bb[2*nip][1] = t4[1];
                bb[2*nip+1][0] = t4[2]; bb[2*nip+1][1] = t4[3];
            }
            #pragma unroll
            for (int mi = 0; mi < 2; mi++)
                #pragma unroll
                for (int ni = 0; ni < 8; ni++)
                    mma16816(acc[mi][ni], ah[mi], bb[ni]);
        }
    }

    #pragma unroll
    for (int mi = 0; mi < 2; mi++) {
        const int r0 = m0 + wm * 32 + mi * 16 + (lane >> 2);
        const int r1 = r0 + 8;
        #pragma unroll
        for (int ni = 0; ni < 8; ni++) {
            const int col = n0 + wn * 64 + ni * 8 + (lane & 3) * 2;
            if (col >= N) continue;
            float b0 = 0.f, b1 = 0.f;
            if (bias) { b0 = bias[col]; b1 = bias[col + 1]; }
            *(float2*)(C + (long)r0 * ldc + col) = make_float2(acc[mi][ni][0] + b0, acc[mi][ni][1] + b1);
            *(float2*)(C + (long)r1 * ldc + col) = make_float2(acc[mi][ni][2] + b0, acc[mi][ni][3] + b1);
        }
    }
}

// ===================== compacted single-product GEMM for fc (rowmap-parameterized) ============
__global__ __launch_bounds__(256, 2)
void mma_gemm_fc(const __half* __restrict__ Ah, const __half* __restrict__ Bw,
                 float* __restrict__ C, int ldc, const float* __restrict__ bias,
                 int N, int K,
                 const int* __restrict__ rowmap, const int* __restrict__ nkeptp)
{
    extern __shared__ __align__(16) char smem[];
    __shared__ int rm[64];
    const uint32_t sbase = smem_u32(smem);

    const int tid = threadIdx.x, wid = tid >> 5, lane = tid & 31;
    const int m0 = blockIdx.y * 64, n0 = blockIdx.x * 256;
    const int wm = wid & 1, wn = wid >> 1;

    const int nkept = *nkeptp;
    if (m0 >= nkept) return;

    if (tid < 64) {
        int r = m0 + tid;
        rm[tid] = rowmap[r < nkept ? r : (nkept - 1)];
    }
    __syncthreads();

    const int NC = K >> 5;

    auto issue = [&](int c) {
        if (c < NC) {
            const long kc = (long)c * 32;
            const uint32_t sb = sbase + (c & (S2_NSTG - 1)) * S2_STAGE;
            {
                int row = tid >> 2, kq = tid & 3;
                CP_ASYNC16(sb + row * ROWB + kq * 16,
                           Ah + (long)rm[row] * K + kc + kq * 8);
            }
            #pragma unroll
            for (int i = 0; i < 4; i++) {
                int ch = tid + i * 256;
                int row = ch >> 2, kq = ch & 3;
                int gr = n0 + row;
                if (gr >= N) gr = N - 1;
                CP_ASYNC16(sb + ATILE + row * ROWB + kq * 16,
                           Bw + (long)gr * K + kc + kq * 8);
            }
        }
        CP_COMMIT();
    };

    float acc[2][8][4];
    #pragma unroll
    for (int mi = 0; mi < 2; mi++)
        #pragma unroll
        for (int ni = 0; ni < 8; ni++)
            #pragma unroll
            for (int q = 0; q < 4; q++) acc[mi][ni][q] = 0.f;

    const uint32_t a_off = (uint32_t)((wm * 32 + (lane & 15)) * ROWB + (lane >> 4) * 16);
    const uint32_t b_off = (uint32_t)((wn * 64 + ((lane >> 4) & 1) * 8 + (lane & 7)) * ROWB
                                      + ((lane >> 3) & 1) * 16);

    issue(0); issue(1); issue(2);

    for (int c = 0; c < NC; c++) {
        CP_WAIT2();
        __syncthreads();
        issue(c + 3);

        const uint32_t tb = sbase + (c & (S2_NSTG - 1)) * S2_STAGE;
        #pragma unroll
        for (int kk = 0; kk < 2; kk++) {
            const uint32_t kba = kk * 32;
            uint32_t ah[2][4], bb[8][2];
            #pragma unroll
            for (int mi = 0; mi < 2; mi++)
                ldsm4(ah[mi], tb + a_off + mi * 16 * ROWB + kba);
            #pragma unroll
            for (int nip = 0; nip < 4; nip++) {
                uint32_t t4[4];
                ldsm4(t4, tb + ATILE + b_off + nip * 16 * ROWB + kba);
                bb[2*nip][0] = t4[0]; bb[2*nip][1] = t4[1];
                bb[2*nip+1][0] = t4[2]; bb[2*nip+1][1] = t4[3];
            }
            #pragma unroll
            for (int mi = 0; mi < 2; mi++)
                #pragma unroll
                for (int ni = 0; ni < 8; ni++)
                    mma16816(acc[mi][ni], ah[mi], bb[ni]);
        }
    }

    #pragma unroll
    for (int mi = 0; mi < 2; mi++) {
        const int l0 = wm * 32 + mi * 16 + (lane >> 2);
        const int l1 = l0 + 8;
        const bool v0r = (m0 + l0) < nkept;
        const bool v1r = (m0 + l1) < nkept;
        const long or0 = (long)rm[l0] * ldc;
        const long or1 = (long)rm[l1] * ldc;
        #pragma unroll
        for (int ni = 0; ni < 8; ni++) {
            const int col = n0 + wn * 64 + ni * 8 + (lane & 3) * 2;
            if (col >= N) continue;
            float b0 = bias[col], b1 = bias[col + 1];
            if (v0r) *(float2*)(C + or0 + col) = make_float2(acc[mi][ni][0] + b0, acc[mi][ni][1] + b1);
            if (v1r) *(float2*)(C + or1 + col) = make_float2(acc[mi][ni][2] + b0, acc[mi][ni][3] + b1);
        }
    }
}

// build rowmaps: rm0 = t==0 (always kept), rmA = kept 1<=t<=7, rmB = kept t>=8
__global__ void k_rowmap(const int* __restrict__ lengths)
{
    __shared__ int cntA[256], cntB[256];
    const int tid = threadIdx.x;
    const int base = tid * 10;
    int fA[10], fB[10];
    int cA = 0, cB = 0;
    #pragma unroll
    for (int i = 0; i < 10; i++) {
        int r = base + i;
        int tt = r % Tn;
        int keep = (lengths[r / Tn] >= tt) ? 1 : 0;
        fA[i] = keep && (tt >= 1) && (tt <= 7);
        fB[i] = keep && (tt >= 8);
        cA += fA[i]; cB += fB[i];
    }
    cntA[tid] = cA; cntB[tid] = cB;
    __syncthreads();
    for (int off = 1; off < 256; off <<= 1) {
        int vA = (tid >= off) ? cntA[tid - off] : 0;
        int vB = (tid >= off) ? cntB[tid - off] : 0;
        __syncthreads();
        cntA[tid] += vA; cntB[tid] += vB;
        __syncthreads();
    }
    int pA = cntA[tid] - cA, pB = cntB[tid] - cB;
    #pragma unroll
    for (int i = 0; i < 10; i++) {
        if (fA[i]) g_rowmapA[pA++] = base + i;
        if (fB[i]) g_rowmapB[pB++] = base + i;
    }
    if (tid < 128) g_rowmap0[tid] = tid * Tn;    // t==0 rows, always kept
    if (tid == 255) { g_nkA = cntA[255]; g_nkB = cntB[255]; g_nk0 = 128; }
}

__global__ void k_zero_masked(const int* __restrict__ lengths, float* __restrict__ out)
{
    const int r = blockIdx.x;
    if (lengths[r / Tn] >= (r % Tn)) return;
    float4* o = (float4*)(out + (long)r * Vn);
    for (int i = threadIdx.x; i < Vn / 4; i += blockDim.x)
        o[i] = make_float4(0.f, 0.f, 0.f, 0.f);
}

// ===================== persistent LSTM (parameterized step range) =====================
#define LB_ALL   (16 * 64 * ROWB)            // 81920
#define LA_STAGE (2 * BTILE)                 // 20480
#define LA_NSTG  4
#define LP_SMEM  (LB_ALL + LA_NSTG * LA_STAGE)   // 163840

__global__ __launch_bounds__(256, 1)
void k_lstm_all(int tbeg, int tend)
{
    extern __shared__ __align__(16) char smem[];
    const uint32_t sbase = smem_u32(smem);
    const int tid = threadIdx.x, wid = tid >> 5, lane = tid & 31;
    const int h0 = blockIdx.x * 16;
    const int wm = wid & 1, wn = wid >> 1;

    {
        int row = tid >> 2, kq = tid & 3;
        int j = (row >> 4) * 512 + h0 + (row & 15);
        const __half* base = g_whh + (long)j * Hn + kq * 8;
        #pragma unroll
        for (int c = 0; c < 16; c++)
            CP_ASYNC16(sbase + c * (64 * ROWB) + row * ROWB + kq * 16, base + c * 32);
        CP_COMMIT();
        CP_WAIT0();
    }
    __syncthreads();

    const uint32_t a_off = (uint32_t)((wm * 64 + (lane & 15)) * ROWB + (lane >> 4) * 16);
    const uint32_t b_off = (uint32_t)((wn * 16 + ((lane >> 4) & 1) * 8 + (lane & 7)) * ROWB
                                      + ((lane >> 3) & 1) * 16);
    const uint32_t aring = sbase + LB_ALL;

    for (int t = tbeg; t < tend; t++) {
        auto issueA = [&](int c) {
            if (c < 16) {
                const long kc = (long)c * 32;
                const uint32_t sb = aring + (c & (LA_NSTG - 1)) * LA_STAGE;
                #pragma unroll
                for (int s = 0; s < 2; s++) {
                    const __half* S = s ? g_hs_l : g_hs_h;
                    #pragma unroll
                    for (int i = 0; i < 2; i++) {
                        int ch = tid + i * 256;
                        int row = ch >> 2, kq = ch & 3;
                        const __half* src = S + ((long)row * Tn + (t - 1)) * Hn + kc + kq * 8;
                        CP_ASYNC16(sb + s * BTILE + row * ROWB + kq * 16, src);
                    }
                }
            }
            CP_COMMIT();
        };

        float acc[4][2][4];
        #pragma unroll
        for (int mi = 0; mi < 4; mi++)
            #pragma unroll
            for (int ni = 0; ni < 2; ni++)
                #pragma unroll
                for (int q = 0; q < 4; q++) acc[mi][ni][q] = 0.f;

        issueA(0); issueA(1); issueA(2);

        for (int c = 0; c < 16; c++) {
            CP_WAIT2();
            __syncthreads();
            issueA(c + 3);

            const uint32_t ta = aring + (c & (LA_NSTG - 1)) * LA_STAGE;
            const uint32_t tbB = sbase + c * (64 * ROWB);
            #pragma unroll
            for (int kk = 0; kk < 2; kk++) {
                const uint32_t kba = kk * 32;
                uint32_t ah[4][4], al[4][4], bb[2][2];
                #pragma unroll
                for (int mi = 0; mi < 4; mi++) {
                    ldsm4(ah[mi], ta + 0 * BTILE + a_off + mi * 16 * ROWB + kba);
                    ldsm4(al[mi], ta + 1 * BTILE + a_off + mi * 16 * ROWB + kba);
                }
                {
                    uint32_t t4[4];
                    ldsm4(t4, tbB + b_off + kba);
                    bb[0][0] = t4[0]; bb[0][1] = t4[1]; bb[1][0] = t4[2]; bb[1][1] = t4[3];
                }
                #pragma unroll
                for (int mi = 0; mi < 4; mi++)
                    #pragma unroll
                    for (int ni = 0; ni < 2; ni++) {
                        mma16816(acc[mi][ni], ah[mi], bb[ni]);
                        mma16816(acc[mi][ni], al[mi], bb[ni]);
                    }
            }
        }

        __syncthreads();
        float* Gs = (float*)(smem + LB_ALL);
        #pragma unroll
        for (int mi = 0; mi < 4; mi++) {
            const int r0 = wm * 64 + mi * 16 + (lane >> 2);
            const int r1 = r0 + 8;
            #pragma unroll
            for (int ni = 0; ni < 2; ni++) {
                const int cl = wn * 16 + ni * 8 + (lane & 3) * 2;
                Gs[r0 * 68 + cl]     = acc[mi][ni][0];
                Gs[r0 * 68 + cl + 1] = acc[mi][ni][1];
                Gs[r1 * 68 + cl]     = acc[mi][ni][2];
                Gs[r1 * 68 + cl + 1] = acc[mi][ni][3];
            }
        }
        __syncthreads();

        for (int p = tid; p < 128 * 16; p += 256) {
            const int b = p >> 4, l = p & 15;
            const int hcol = h0 + l;
            const float* xg = g_xg + ((long)b * Tn + t) * 2048;
            float gi = Gs[b * 68 + 0 * 16 + l] + xg[0 * 512 + hcol];
            float gf = Gs[b * 68 + 1 * 16 + l] + xg[1 * 512 + hcol];
            float gg = Gs[b * 68 + 2 * 16 + l] + xg[2 * 512 + hcol];
            float go = Gs[b * 68 + 3 * 16 + l] + xg[3 * 512 + hcol];
            float co = g_c[b * 512 + hcol];
            float si = 1.f / (1.f + __expf(-gi));
            float sf = 1.f / (1.f + __expf(-gf));
            float so = 1.f / (1.f + __expf(-go));
            float cn = sf * co + si * tanhf(gg);
            float hn = so * tanhf(cn);
            g_c[b * 512 + hcol] = cn;
            split_write16(hn, g_hs_h, g_hs_l, ((long)b * Tn + t) * 512 + hcol);
        }

        __syncthreads();
        if (tid == 0) {
            __threadfence();
            atomicAdd(&g_bar, 1u);
            while (*(volatile unsigned*)&g_bar < 32u * (unsigned)t) { }
            __threadfence();
        }
        __syncthreads();
    }
}

__global__ void k_lstm_t0()
{
    int i = blockIdx.x * blockDim.x + threadIdx.x;
    if (i == 0) g_bar = 0u;
    if (i >= Bn * Hn) return;
    int b = i >> 9, hcol = i & 511;
    const float* xg = g_xg + ((long)b * Tn) * 2048;
    float gi = xg[hcol], gg = xg[1024 + hcol], go = xg[1536 + hcol];
    float si = 1.f / (1.f + __expf(-gi));
    float so = 1.f / (1.f + __expf(-go));
    float cn = si * tanhf(gg);
    float hn = so * tanhf(cn);
    g_c[i] = cn;
    split_write16(hn, g_hs_h, g_hs_l, ((long)b * Tn) * 512 + hcol);
}

// ===================== split-K fp32 GEMM for img =====================
__global__ __launch_bounds__(256)
void sgemm_splitk(const float* __restrict__ A, const float* __restrict__ Bw)
{
    __shared__ float As[16][64];
    __shared__ float Bs[16][64];
    const int tid = threadIdx.x;
    const int tx = tid & 15, ty = tid >> 4;
    const int n0 = blockIdx.x * 64, m0 = blockIdx.y * 64;
    const int kbase = blockIdx.z * 256;
    const int lr = tid >> 2, lk = (tid & 3) * 4;
    const float* Ap = A  + (long)(m0 + lr) * 2048 + kbase + lk;
    const float* Bp = Bw + (long)(n0 + lr) * 2048 + kbase + lk;

    float acc[4][4] = {};
    for (int k0 = 0; k0 < 256; k0 += 16) {
        float4 avv = *(const float4*)(Ap + k0);
        float4 bvv = *(const float4*)(Bp + k0);
        __syncthreads();
        As[lk+0][lr] = avv.x; As[lk+1][lr] = avv.y; As[lk+2][lr] = avv.z; As[lk+3][lr] = avv.w;
        Bs[lk+0][lr] = bvv.x; Bs[lk+1][lr] = bvv.y; Bs[lk+2][lr] = bvv.z; Bs[lk+3][lr] = bvv.w;
        __syncthreads();
        #pragma unroll
        for (int kk = 0; kk < 16; kk++) {
            float a[4], b[4];
            #pragma unroll
            for (int i = 0; i < 4; i++) a[i] = As[kk][ty * 4 + i];
            #pragma unroll
            for (int j = 0; j < 4; j++) b[j] = Bs[kk][tx * 4 + j];
            #pragma unroll
            for (int i = 0; i < 4; i++)
                #pragma unroll
                for (int j = 0; j < 4; j++) acc[i][j] += a[i] * b[j];
        }
    }
    float* Cp = g_part + (long)blockIdx.z * Bn * VISn;
    #pragma unroll
    for (int i = 0; i < 4; i++)
        #pragma unroll
        for (int j = 0; j < 4; j++)
            Cp[(long)(m0 + ty * 4 + i) * VISn + n0 + tx * 4 + j] = acc[i][j];
}

__global__ void k_img_reduce(const float* __restrict__ img_b) {
    int b = blockIdx.x, v = threadIdx.x;
    float s = img_b[v];
    #pragma unroll
    for (int k = 0; k < 8; k++) s += g_part[((long)k * Bn + b) * VISn + v];
    g_x16[(long)(b * Tn) * 1024 + v] = __float2half_rn(s);
}

// ===================== prep kernels =====================
__global__ void k_bias2(const float* __restrict__ b_ih, const float* __restrict__ b_hh) {
    int i = blockIdx.x * blockDim.x + threadIdx.x;
    if (i < 4 * Hn) g_bias2[i] = b_ih[i] + b_hh[i];
}
__global__ void k_cvt16(const float* __restrict__ x, __half* __restrict__ h, int n4) {
    int i = blockIdx.x * blockDim.x + threadIdx.x;
    if (i >= n4) return;
    float4 v = ((const float4*)x)[i];
    __half2 a = __floats2half2_rn(v.x, v.y);
    __half2 b = __floats2half2_rn(v.z, v.w);
    ((uint2*)h)[i] = make_uint2(*(uint32_t*)&a, *(uint32_t*)&b);
}
__global__ void k_transpose_f(const float* __restrict__ features) {
    int bp = blockIdx.x;
    int b = bp / 49, p = bp % 49;
    int v = threadIdx.x;
    g_fT[(long)bp * 512 + v] =
        __float2half_rn(features[((long)b * 512 + v) * 49 + p]);
}
__global__ void k_normalize() {
    int row = blockIdx.x;
    int b = row / 49, p = row % 49;
    const float* x = g_fv + (long)row * 512;
    __shared__ float red[8];
    int tid = threadIdx.x, lane = tid & 31, wid = tid >> 5;
    float s = 0.f;
    for (int v = tid; v < 512; v += 256) { float t = x[v]; s += t * t; }
    #pragma unroll
    for (int o = 16; o; o >>= 1) s += __shfl_xor_sync(0xffffffffu, s, o);
    if (lane == 0) red[wid] = s;
    __syncthreads();
    if (tid == 0) {
        float sum = 0.f;
        #pragma unroll
        for (int w = 0; w < 8; w++) sum += red[w];
        red[0] = 1.f / fmaxf(sqrtf(sum), 1e-12f);
    }
    __syncthreads();
    float inv = red[0];
    long o = ((long)b * 64 + p) * 512;
    for (int v = tid; v < 512; v += 256) {
        float val = x[v] * inv;
        g_features_all[o + v] = val;
        g_fall16[o + v] = __float2half_rn(val);
    }
}
__global__ void k_copy_eng(const float* __restrict__ eng) {
    int bj = blockIdx.x;
    int b = bj / 15, j = bj % 15;
    int v = threadIdx.x;
    float val = eng[(long)bj * 512 + v];
    long o = ((long)b * 64 + 49 + j) * 512 + v;
    g_features_all[o] = val;
    g_fall16[o] = __float2half_rn(val);
}
__global__ void k_embed(const int* __restrict__ captions, const float* __restrict__ embed_w) {
    int r = blockIdx.x;
    int idx = captions[r];
    float v = embed_w[(long)idx * 512 + threadIdx.x];
    __half hv = __float2half_rn(v);
    g_we16[(long)r * 512 + threadIdx.x] = hv;
    g_x16[(long)r * 1024 + 512 + threadIdx.x] = hv;
}

// ===================== attention: scores =====================
__global__ __launch_bounds__(256)
void k_att_scores(const float* __restrict__ att_bias, const float* __restrict__ att_w) {
    const int n0 = blockIdx.x * 8, b = blockIdx.y;
    __shared__ float fea8[8][512];
    __shared__ float ws[512];
    __shared__ float hh[512];
    const int tid = threadIdx.x, lane = tid & 31, wid = tid >> 5;

    for (int v = tid; v < 512; v += 256) ws[v] = att_w[v];
    const float4* fea = (const float4*)(g_att_fea + ((long)b * 64 + n0) * 512);
    for (int i = tid; i < 8 * 128; i += 256)
        ((float4*)&fea8[0][0])[i] = fea[i];
    const float bn = att_bias[n0 + wid];

    for (int t = 0; t < Tn - 1; t++) {
        __syncthreads();
        for (int v = tid; v < 512; v += 256) hh[v] = g_att_h[((long)b * Tn + t) * 512 + v];
        __syncthreads();
        float s = 0.f;
        #pragma unroll 4
        for (int v = lane; v < 512; v += 32)
            s += fmaxf(fea8[wid][v] + hh[v] + bn, 0.f) * ws[v];
        #pragma unroll
        for (int o = 16; o; o >>= 1) s += __shfl_xor_sync(0xffffffffu, s, o);
        if (lane == 0) g_scores[((long)b * (Tn - 1) + t) * 64 + n0 + wid] = s;
    }
}

// ===================== attention: softmax + context =====================
#define CTX_SMEM (64 * 512 * 4 + 256)
__global__ __launch_bounds__(512)
void k_att_ctx() {
    extern __shared__ float fs[];
    float* sout = fs + 64 * 512;
    const int b = blockIdx.x, tid = threadIdx.x, lane = tid & 31, wid = tid >> 5;

    const float4* src = (const float4*)(g_features_all + (long)b * 64 * 512);
    for (int i = tid; i < 64 * 128; i += 512) ((float4*)fs)[i] = src[i];
    __syncthreads();

    for (int t = 0; t < Tn - 1; t++) {
        if (wid == 0) {
            const float* sc = g_scores + ((long)b * (Tn - 1) + t) * 64;
            float s0 = sc[lane], s1 = sc[lane + 32];
            float m = fmaxf(s0, s1);
            #pragma unroll
            for (int o = 16; o; o >>= 1) m = fmaxf(m, __shfl_xor_sync(0xffffffffu, m, o));
            float e0 = __expf(s0 - m), e1 = __expf(s1 - m);
            float sum = e0 + e1;
            #pragma unroll
            for (int o = 16; o; o >>= 1) sum += __shfl_xor_sync(0xffffffffu, sum, o);
            float inv = 1.f / sum;
            sout[lane] = e0 * inv; sout[lane + 32] = e1 * inv;
        }
        __syncthreads();
        float acc = 0.f;
        #pragma unroll 8
        for (int n = 0; n < 64; n++) acc += sout[n] * fs[n * 512 + tid];
        g_x16[((long)b * Tn + (t + 1)) * 1024 + tid] = __float2half_rn(acc);
        __syncthreads();
    }
}

// ===================== launch =====================
static inline dim3 tgrid256(int M, int N) { return dim3((N + 255) / 256, (M + 63) / 64); }

extern "C" void kernel_launch(void* const* d_in, const int* in_sizes, int n_in,
                              void* d_out, int out_size)
{
    const float* feature_0 = (const float*)d_in[0];
    const float* features  = (const float*)d_in[1];
    const float* eng       = (const float*)d_in[2];
    const int*   captions  = (const int*)  d_in[3];
    const int*   lengths   = (const int*)  d_in[4];
    const float* embed_w   = (const float*)d_in[5];
    const float* w_ih      = (const float*)d_in[6];
    const float* w_hh      = (const float*)d_in[7];
    const float* b_ih      = (const float*)d_in[8];
    const float* b_hh      = (const float*)d_in[9];
    const float* fc_w      = (const float*)d_in[10];
    const float* fc_b      = (const float*)d_in[11];
    const float* att_vw_w  = (const float*)d_in[12];
    const float* att_hw_w  = (const float*)d_in[13];
    const float* att_bias  = (const float*)d_in[14];
    const float* att_w_w   = (const float*)d_in[15];
    const float* att_fc_w  = (const float*)d_in[16];
    const float* att_fc_b  = (const float*)d_in[17];
    const float* img_w     = (const float*)d_in[18];
    const float* img_b     = (const float*)d_in[19];
    float* out = (float*)d_out;

    static bool init_done = false;
    static cudaStream_t s1;
    static cudaEvent_t ev0, ev1, ev3, evEnd, evT0, evL1, evFcA;
    if (!init_done) {
        cudaFuncSetAttribute(mma_gemm1,   cudaFuncAttributeMaxDynamicSharedMemorySize, S2_SMEM);
        cudaFuncSetAttribute(mma_gemm_fc, cudaFuncAttributeMaxDynamicSharedMemorySize, S2_SMEM);
        cudaFuncSetAttribute(k_lstm_all,  cudaFuncAttributeMaxDynamicSharedMemorySize, LP_SMEM);
        cudaFuncSetAttribute(k_att_ctx,   cudaFuncAttributeMaxDynamicSharedMemorySize, CTX_SMEM);
        cudaStreamCreateWithFlags(&s1, cudaStreamNonBlocking);
        cudaEventCreateWithFlags(&ev0,   cudaEventDisableTiming);
        cudaEventCreateWithFlags(&ev1,   cudaEventDisableTiming);
        cudaEventCreateWithFlags(&ev3,   cudaEventDisableTiming);
        cudaEventCreateWithFlags(&evEnd, cudaEventDisableTiming);
        cudaEventCreateWithFlags(&evT0,  cudaEventDisableTiming);
        cudaEventCreateWithFlags(&evL1,  cudaEventDisableTiming);
        cudaEventCreateWithFlags(&evFcA, cudaEventDisableTiming);
        init_done = true;
    }

    float* p_fv = nullptr;    cudaGetSymbolAddress((void**)&p_fv,    g_fv);
    float* p_ah = nullptr;    cudaGetSymbolAddress((void**)&p_ah,    g_att_h);
    float* p_xg = nullptr;    cudaGetSymbolAddress((void**)&p_xg,    g_xg);
    float* p_bias2 = nullptr; cudaGetSymbolAddress((void**)&p_bias2, g_bias2);
    float* p_afea = nullptr;  cudaGetSymbolAddress((void**)&p_afea,  g_att_fea);
    int* p_rm0 = nullptr;     cudaGetSymbolAddress((void**)&p_rm0,   g_rowmap0);
    int* p_rmA = nullptr;     cudaGetSymbolAddress((void**)&p_rmA,   g_rowmapA);
    int* p_rmB = nullptr;     cudaGetSymbolAddress((void**)&p_rmB,   g_rowmapB);
    int* p_nk0 = nullptr;     cudaGetSymbolAddress((void**)&p_nk0,   g_nk0);
    int* p_nkA = nullptr;     cudaGetSymbolAddress((void**)&p_nkA,   g_nkA);
    int* p_nkB = nullptr;     cudaGetSymbolAddress((void**)&p_nkB,   g_nkB);
    #define HSYM(p, s) __half* p = nullptr; cudaGetSymbolAddress((void**)&p, s)
    HSYM(p_fT, g_fT);
    HSYM(p_fall16, g_fall16);
    HSYM(p_we16, g_we16);
    HSYM(p_x16, g_x16);
    HSYM(p_hs_h, g_hs_h);
    HSYM(p_wfc1, g_wfc1);     HSYM(p_wvw, g_wvw);
    HSYM(p_whw, g_whw);       HSYM(p_wih, g_wih);
    HSYM(p_wfc, g_wfc);       HSYM(p_whh, g_whh);
    #undef HSYM

    // ---- fork: side stream s1 handles all off-critical-path work ----
    cudaEventRecord(ev0, 0);
    cudaStreamWaitEvent(s1, ev0, 0);

    // side stream: early deps for att_fea/scores
    k_cvt16<<<(512 * 512 / 4 + 255) / 256, 256, 0, s1>>>(att_vw_w, p_wvw, 512 * 512 / 4);
    k_copy_eng<<<Bn * 15, 512, 0, s1>>>(eng);
    k_embed<<<Bn * Tn, 512, 0, s1>>>(captions, embed_w);
    k_cvt16<<<(512 * 512 / 4 + 255) / 256, 256, 0, s1>>>(att_hw_w, p_whw, 512 * 512 / 4);
    mma_gemm1<<<tgrid256(Bn * Tn, 512), 256, S2_SMEM, s1>>>(p_we16, p_whw,
        p_ah, 512, nullptr, 512, 512);                       // att_h
    cudaEventRecord(ev1, s1);

    // side stream: deps for xg / LSTM
    k_cvt16<<<(2048 * 1024 / 4 + 255) / 256, 256, 0, s1>>>(w_ih, p_wih, 2048 * 1024 / 4);
    sgemm_splitk<<<dim3(8, 2, 8), 256, 0, s1>>>(feature_0, img_w);
    k_img_reduce<<<Bn, 512, 0, s1>>>(img_b);
    k_bias2<<<(4 * Hn + 255) / 256, 256, 0, s1>>>(b_ih, b_hh);
    k_cvt16<<<(2048 * 512 / 4 + 255) / 256, 256, 0, s1>>>(w_hh, p_whh, 2048 * 512 / 4);
    cudaEventRecord(ev3, s1);

    // side stream: deps for fc
    k_cvt16<<<(Vn * 512 / 4 + 255) / 256, 256, 0, s1>>>(fc_w, p_wfc, Vn * 512 / 4);
    k_rowmap<<<1, 256, 0, s1>>>(lengths);
    k_zero_masked<<<Bn * Tn, 256, 0, s1>>>(lengths, out);
    cudaEventRecord(evEnd, s1);

    // ---- main stream: critical chain ----
    k_cvt16<<<(512 * 512 / 4 + 255) / 256, 256>>>(att_fc_w, p_wfc1, 512 * 512 / 4);
    k_transpose_f<<<Bn * 49, 512>>>(features);

    // att_fc: fv = fT @ att_fc_w.T + b
    mma_gemm1<<<tgrid256(Bn * 49, 512), 256, S2_SMEM>>>(p_fT, p_wfc1,
        p_fv, 512, att_fc_b, 512, 512);
    k_normalize<<<Bn * 49, 256>>>();

    cudaStreamWaitEvent(0, ev1, 0);   // wvw, copy_eng, att_h ready

    // att_fea = features_all @ att_vw_w.T
    mma_gemm1<<<tgrid256(Bn * 64, 512), 256, S2_SMEM>>>(p_fall16, p_wvw,
        p_afea, 512, nullptr, 512, 512);

    // attention: scores then softmax+context -> g_x16 rows t=1..19
    k_att_scores<<<dim3(8, Bn), 256>>>(att_bias, att_w_w);
    k_att_ctx<<<Bn, 512, CTX_SMEM>>>();

    cudaStreamWaitEvent(0, ev3, 0);   // wih, img, bias2, whh ready

    // xg = [feas|we] @ w_ih.T + (b_ih+b_hh)
    mma_gemm1<<<tgrid256(Bn * Tn, 4 * Hn), 256, S2_SMEM>>>(p_x16, p_wih,
        p_xg, 4 * Hn, p_bias2, 4 * Hn, 1024);

    // LSTM step 0 (also resets global barrier), then part 1 (steps 1..7)
    k_lstm_t0<<<(Bn * Hn + 255) / 256, 256>>>();
    cudaEventRecord(evT0, 0);
    k_lstm_all<<<32, 256, LP_SMEM>>>(1, 8);
    cudaEventRecord(evL1, 0);

    // side stream: fc0 (t==0 rows) overlaps LSTM part 1; fcA (1<=t<=7) overlaps part 2
    cudaStreamWaitEvent(s1, evT0, 0);   // h rows t=0 ready (wfc/rowmap/zero by s1 order)
    mma_gemm_fc<<<tgrid256(128, Vn), 256, S2_SMEM, s1>>>(p_hs_h, p_wfc,
        out, Vn, fc_b, Vn, 512, p_rm0, p_nk0);
    cudaStreamWaitEvent(s1, evL1, 0);   // h rows t<=7 ready
    mma_gemm_fc<<<tgrid256(128 * 7, Vn), 256, S2_SMEM, s1>>>(p_hs_h, p_wfc,
        out, Vn, fc_b, Vn, 512, p_rmA, p_nkA);
    cudaEventRecord(evFcA, s1);

    // main: LSTM part 2 (steps 8..19), then fcB (rows t>=8)
    k_lstm_all<<<32, 256, LP_SMEM>>>(8, 20);
    cudaStreamWaitEvent(0, evEnd, 0);   // wfc, rowmap, zero_masked done
    mma_gemm_fc<<<tgrid256(128 * 12, Vn), 256, S2_SMEM>>>(p_hs_h, p_wfc,
        out, Vn, fc_b, Vn, 512, p_rmB, p_nkB);

    // join side branch before capture end
    cudaStreamWaitEvent(0, evFcA, 0);
}

// round 17
// speedup vs baseline: 1.0631x; 1.0631x over previous
#include <cuda_runtime.h>
#include <cuda_fp16.h>
#include <cstdint>
#include <math.h>

// Problem dims
#define Bn   128
#define Tn   20
#define Vn   12000
#define En   512
#define Hn   512
#define VISn 512

// ===================== PTX helpers (sm_100 baseline) =====================
__device__ __forceinline__ uint32_t smem_u32(const void* p) {
    uint32_t a;
    asm("{ .reg .u64 t; cvta.to.shared.u64 t, %1; cvt.u32.u64 %0, t; }" : "=r"(a) : "l"(p));
    return a;
}
#define CP_ASYNC16(dst, src) \
    asm volatile("cp.async.cg.shared.global [%0], [%1], 16;" :: "r"(dst), "l"(src) : "memory")
#define CP_COMMIT() asm volatile("cp.async.commit_group;" ::: "memory")
#define CP_WAIT0()  asm volatile("cp.async.wait_group 0;" ::: "memory")
#define CP_WAIT2()  asm volatile("cp.async.wait_group 2;" ::: "memory")

__device__ __forceinline__ void ldsm4(uint32_t* r, uint32_t addr) {
    asm volatile("ldmatrix.sync.aligned.m8n8.x4.shared.b16 {%0,%1,%2,%3}, [%4];"
        : "=r"(r[0]), "=r"(r[1]), "=r"(r[2]), "=r"(r[3]) : "r"(addr));
}
__device__ __forceinline__ void mma16816(float* c, const uint32_t* a, const uint32_t* b) {
    asm volatile("mma.sync.aligned.m16n8k16.row.col.f32.f16.f16.f32 "
        "{%0,%1,%2,%3}, {%4,%5,%6,%7}, {%8,%9}, {%0,%1,%2,%3};"
        : "+f"(c[0]), "+f"(c[1]), "+f"(c[2]), "+f"(c[3])
        : "r"(a[0]), "r"(a[1]), "r"(a[2]), "r"(a[3]), "r"(b[0]), "r"(b[1]));
}

// ===================== scratch (device globals) =====================
__device__ float g_fv[Bn * 49 * VISn];
__device__ float g_features_all[Bn * 64 * VISn];
__device__ float g_att_fea[Bn * 64 * VISn];
__device__ float g_att_h[Bn * Tn * VISn];
__device__ float g_scores[Bn * (Tn - 1) * 64];
__device__ float g_xg[Bn * Tn * 4 * Hn];
__device__ float g_c[Bn * Hn];
__device__ float g_bias2[4 * Hn];
__device__ float g_part[8 * Bn * VISn];
__device__ unsigned g_bar;
__device__ int g_rowmapA[Bn * Tn];
__device__ int g_rowmapB[Bn * Tn];
__device__ int g_nkA;
__device__ int g_nkB;

// activations (single fp16, except hs which stays split for the recurrent path)
__device__ __half g_fT[Bn * 49 * VISn];
__device__ __half g_fall16[Bn * 64 * VISn];
__device__ __half g_we16[Bn * Tn * En];
__device__ __half g_x16[Bn * Tn * 1024];
__device__ __half g_hs_h[Bn * Tn * Hn], g_hs_l[Bn * Tn * Hn];
// weights: single fp16
__device__ __half g_wfc1[VISn * VISn];
__device__ __half g_wvw[VISn * VISn];
__device__ __half g_whw[VISn * En];
__device__ __half g_wih[4 * Hn * 1024];
__device__ __half g_wfc[Vn * Hn];
__device__ __half g_whh[4 * Hn * Hn];

__device__ __forceinline__ void split_write16(float v, __half* h, __half* l, long i) {
    __half hi = __float2half_rn(v);
    h[i] = hi;
    l[i] = __float2half_rn(v - __half2float(hi));
}

#define ROWB   80
#define ATILE  (64 * ROWB)           // 5120 B
#define BTILE  (128 * ROWB)          // 10240 B
#define B2TILE (256 * ROWB)          // 20480 B

// ===================== single-product GEMM: CTA 64x256, 2 CTAs/SM =====================
#define S2_STAGE (ATILE + B2TILE)        // 25600
#define S2_NSTG  4
#define S2_SMEM  (S2_NSTG * S2_STAGE)    // 102400

__global__ __launch_bounds__(256, 2)
void mma_gemm1(const __half* __restrict__ Ah, const __half* __restrict__ Bw,
               float* __restrict__ C, int ldc, const float* __restrict__ bias,
               int N, int K)
{
    extern __shared__ __align__(16) char smem[];
    const uint32_t sbase = smem_u32(smem);

    const int tid = threadIdx.x, wid = tid >> 5, lane = tid & 31;
    const int m0 = blockIdx.y * 64, n0 = blockIdx.x * 256;
    const int wm = wid & 1, wn = wid >> 1;

    const int NC = K >> 5;

    auto issue = [&](int c) {
        if (c < NC) {
            const long kc = (long)c * 32;
            const uint32_t sb = sbase + (c & (S2_NSTG - 1)) * S2_STAGE;
            {
                int row = tid >> 2, kq = tid & 3;
                CP_ASYNC16(sb + row * ROWB + kq * 16,
                           Ah + (long)(m0 + row) * K + kc + kq * 8);
            }
            #pragma unroll
            for (int i = 0; i < 4; i++) {
                int ch = tid + i * 256;
                int row = ch >> 2, kq = ch & 3;
                int gr = n0 + row;
                if (gr >= N) gr = N - 1;
                CP_ASYNC16(sb + ATILE + row * ROWB + kq * 16,
                           Bw + (long)gr * K + kc + kq * 8);
            }
        }
        CP_COMMIT();
    };

    float acc[2][8][4];
    #pragma unroll
    for (int mi = 0; mi < 2; mi++)
        #pragma unroll
        for (int ni = 0; ni < 8; ni++)
            #pragma unroll
            for (int q = 0; q < 4; q++) acc[mi][ni][q] = 0.f;

    const uint32_t a_off = (uint32_t)((wm * 32 + (lane & 15)) * ROWB + (lane >> 4) * 16);
    const uint32_t b_off = (uint32_t)((wn * 64 + ((lane >> 4) & 1) * 8 + (lane & 7)) * ROWB
                                      + ((lane >> 3) & 1) * 16);

    issue(0); issue(1); issue(2);

    for (int c = 0; c < NC; c++) {
        CP_WAIT2();
        __syncthreads();
        issue(c + 3);

        const uint32_t tb = sbase + (c & (S2_NSTG - 1)) * S2_STAGE;
        #pragma unroll
        for (int kk = 0; kk < 2; kk++) {
            const uint32_t kba = kk * 32;
            uint32_t ah[2][4], bb[8][2];
            #pragma unroll
            for (int mi = 0; mi < 2; mi++)
                ldsm4(ah[mi], tb + a_off + mi * 16 * ROWB + kba);
            #pragma unroll
            for (int nip = 0; nip < 4; nip++) {
                uint32_t t4[4];
                ldsm4(t4, tb + ATILE + b_off + nip * 16 * ROWB + kba);
                bb[2*nip][0] = t4[0]; bb[2*nip][1] = t4[1];
                bb[2*nip+1][0] = t4[2]; bb[2*nip+1][1] = t4[3];
            }
            #pragma unroll
            for (int mi = 0; mi < 2; mi++)
                #pragma unroll
                for (int ni = 0; ni < 8; ni++)
                    mma16816(acc[mi][ni], ah[mi], bb[ni]);
        }
    }

    #pragma unroll
    for (int mi = 0; mi < 2; mi++) {
        const int r0 = m0 + wm * 32 + mi * 16 + (lane >> 2);
        const int r1 = r0 + 8;
        #pragma unroll
        for (int ni = 0; ni < 8; ni++) {
            const int col = n0 + wn * 64 + ni * 8 + (lane & 3) * 2;
            if (col >= N) continue;
            float b0 = 0.f, b1 = 0.f;
            if (bias) { b0 = bias[col]; b1 = bias[col + 1]; }
            *(float2*)(C + (long)r0 * ldc + col) = make_float2(acc[mi][ni][0] + b0, acc[mi][ni][1] + b1);
            *(float2*)(C + (long)r1 * ldc + col) = make_float2(acc[mi][ni][2] + b0, acc[mi][ni][3] + b1);
        }
    }
}

// ===================== compacted single-product GEMM for fc (rowmap-parameterized) ============
__global__ __launch_bounds__(256, 2)
void mma_gemm_fc(const __half* __restrict__ Ah, const __half* __restrict__ Bw,
                 float* __restrict__ C, int ldc, const float* __restrict__ bias,
                 int N, int K,
                 const int* __restrict__ rowmap, const int* __restrict__ nkeptp)
{
    extern __shared__ __align__(16) char smem[];
    __shared__ int rm[64];
    const uint32_t sbase = smem_u32(smem);

    const int tid = threadIdx.x, wid = tid >> 5, lane = tid & 31;
    const int m0 = blockIdx.y * 64, n0 = blockIdx.x * 256;
    const int wm = wid & 1, wn = wid >> 1;

    const int nkept = *nkeptp;
    if (m0 >= nkept) return;

    if (tid < 64) {
        int r = m0 + tid;
        rm[tid] = rowmap[r < nkept ? r : (nkept - 1)];
    }
    __syncthreads();

    const int NC = K >> 5;

    auto issue = [&](int c) {
        if (c < NC) {
            const long kc = (long)c * 32;
            const uint32_t sb = sbase + (c & (S2_NSTG - 1)) * S2_STAGE;
            {
                int row = tid >> 2, kq = tid & 3;
                CP_ASYNC16(sb + row * ROWB + kq * 16,
                           Ah + (long)rm[row] * K + kc + kq * 8);
            }
            #pragma unroll
            for (int i = 0; i < 4; i++) {
                int ch = tid + i * 256;
                int row = ch >> 2, kq = ch & 3;
                int gr = n0 + row;
                if (gr >= N) gr = N - 1;
                CP_ASYNC16(sb + ATILE + row * ROWB + kq * 16,
                           Bw + (long)gr * K + kc + kq * 8);
            }
        }
        CP_COMMIT();
    };

    float acc[2][8][4];
    #pragma unroll
    for (int mi = 0; mi < 2; mi++)
        #pragma unroll
        for (int ni = 0; ni < 8; ni++)
            #pragma unroll
            for (int q = 0; q < 4; q++) acc[mi][ni][q] = 0.f;

    const uint32_t a_off = (uint32_t)((wm * 32 + (lane & 15)) * ROWB + (lane >> 4) * 16);
    const uint32_t b_off = (uint32_t)((wn * 64 + ((lane >> 4) & 1) * 8 + (lane & 7)) * ROWB
                                      + ((lane >> 3) & 1) * 16);

    issue(0); issue(1); issue(2);

    for (int c = 0; c < NC; c++) {
        CP_WAIT2();
        __syncthreads();
        issue(c + 3);

        const uint32_t tb = sbase + (c & (S2_NSTG - 1)) * S2_STAGE;
        #pragma unroll
        for (int kk = 0; kk < 2; kk++) {
            const uint32_t kba = kk * 32;
            uint32_t ah[2][4], bb[8][2];
            #pragma unroll
            for (int mi = 0; mi < 2; mi++)
                ldsm4(ah[mi], tb + a_off + mi * 16 * ROWB + kba);
            #pragma unroll
            for (int nip = 0; nip < 4; nip++) {
                uint32_t t4[4];
                ldsm4(t4, tb + ATILE + b_off + nip * 16 * ROWB + kba);
                bb[2*nip][0] = t4[0]; bb[2*nip][1] = t4[1];
                bb[2*nip+1][0] = t4[2]; bb[2*nip+1][1] = t4[3];
            }
            #pragma unroll
            for (int mi = 0; mi < 2; mi++)
                #pragma unroll
                for (int ni = 0; ni < 8; ni++)
                    mma16816(acc[mi][ni], ah[mi], bb[ni]);
        }
    }

    #pragma unroll
    for (int mi = 0; mi < 2; mi++) {
        const int l0 = wm * 32 + mi * 16 + (lane >> 2);
        const int l1 = l0 + 8;
        const bool v0r = (m0 + l0) < nkept;
        const bool v1r = (m0 + l1) < nkept;
        const long or0 = (long)rm[l0] * ldc;
        const long or1 = (long)rm[l1] * ldc;
        #pragma unroll
        for (int ni = 0; ni < 8; ni++) {
            const int col = n0 + wn * 64 + ni * 8 + (lane & 3) * 2;
            if (col >= N) continue;
            float b0 = bias[col], b1 = bias[col + 1];
            if (v0r) *(float2*)(C + or0 + col) = make_float2(acc[mi][ni][0] + b0, acc[mi][ni][1] + b1);
            if (v1r) *(float2*)(C + or1 + col) = make_float2(acc[mi][ni][2] + b0, acc[mi][ni][3] + b1);
        }
    }
}

// build rowmaps of kept rows split by timestep: A = t<=9, B = t>=10
__global__ void k_rowmap(const int* __restrict__ lengths)
{
    __shared__ int cntA[256], cntB[256];
    const int tid = threadIdx.x;
    const int base = tid * 10;
    int fA[10], fB[10];
    int cA = 0, cB = 0;
    #pragma unroll
    for (int i = 0; i < 10; i++) {
        int r = base + i;
        int tt = r % Tn;
        int keep = (lengths[r / Tn] >= tt) ? 1 : 0;
        fA[i] = keep && (tt <= 9);
        fB[i] = keep && (tt >= 10);
        cA += fA[i]; cB += fB[i];
    }
    cntA[tid] = cA; cntB[tid] = cB;
    __syncthreads();
    for (int off = 1; off < 256; off <<= 1) {
        int vA = (tid >= off) ? cntA[tid - off] : 0;
        int vB = (tid >= off) ? cntB[tid - off] : 0;
        __syncthreads();
        cntA[tid] += vA; cntB[tid] += vB;
        __syncthreads();
    }
    int pA = cntA[tid] - cA, pB = cntB[tid] - cB;
    #pragma unroll
    for (int i = 0; i < 10; i++) {
        if (fA[i]) g_rowmapA[pA++] = base + i;
        if (fB[i]) g_rowmapB[pB++] = base + i;
    }
    if (tid == 255) { g_nkA = cntA[255]; g_nkB = cntB[255]; }
}

__global__ void k_zero_masked(const int* __restrict__ lengths, float* __restrict__ out)
{
    const int r = blockIdx.x;
    if (lengths[r / Tn] >= (r % Tn)) return;
    float4* o = (float4*)(out + (long)r * Vn);
    for (int i = threadIdx.x; i < Vn / 4; i += blockDim.x)
        o[i] = make_float4(0.f, 0.f, 0.f, 0.f);
}

// ===================== persistent LSTM (parameterized step range) =====================
#define LB_ALL   (16 * 64 * ROWB)            // 81920
#define LA_STAGE (2 * BTILE)                 // 20480
#define LA_NSTG  4
#define LP_SMEM  (LB_ALL + LA_NSTG * LA_STAGE)   // 163840

__global__ __launch_bounds__(256, 1)
void k_lstm_all(int tbeg, int tend)
{
    extern __shared__ __align__(16) char smem[];
    const uint32_t sbase = smem_u32(smem);
    const int tid = threadIdx.x, wid = tid >> 5, lane = tid & 31;
    const int h0 = blockIdx.x * 16;
    const int wm = wid & 1, wn = wid >> 1;

    {
        int row = tid >> 2, kq = tid & 3;
        int j = (row >> 4) * 512 + h0 + (row & 15);
        const __half* base = g_whh + (long)j * Hn + kq * 8;
        #pragma unroll
        for (int c = 0; c < 16; c++)
            CP_ASYNC16(sbase + c * (64 * ROWB) + row * ROWB + kq * 16, base + c * 32);
        CP_COMMIT();
        CP_WAIT0();
    }
    __syncthreads();

    const uint32_t a_off = (uint32_t)((wm * 64 + (lane & 15)) * ROWB + (lane >> 4) * 16);
    const uint32_t b_off = (uint32_t)((wn * 16 + ((lane >> 4) & 1) * 8 + (lane & 7)) * ROWB
                                      + ((lane >> 3) & 1) * 16);
    const uint32_t aring = sbase + LB_ALL;

    for (int t = tbeg; t < tend; t++) {
        auto issueA = [&](int c) {
            if (c < 16) {
                const long kc = (long)c * 32;
                const uint32_t sb = aring + (c & (LA_NSTG - 1)) * LA_STAGE;
                #pragma unroll
                for (int s = 0; s < 2; s++) {
                    const __half* S = s ? g_hs_l : g_hs_h;
                    #pragma unroll
                    for (int i = 0; i < 2; i++) {
                        int ch = tid + i * 256;
                        int row = ch >> 2, kq = ch & 3;
                        const __half* src = S + ((long)row * Tn + (t - 1)) * Hn + kc + kq * 8;
                        CP_ASYNC16(sb + s * BTILE + row * ROWB + kq * 16, src);
                    }
                }
            }
            CP_COMMIT();
        };

        float acc[4][2][4];
        #pragma unroll
        for (int mi = 0; mi < 4; mi++)
            #pragma unroll
            for (int ni = 0; ni < 2; ni++)
                #pragma unroll
                for (int q = 0; q < 4; q++) acc[mi][ni][q] = 0.f;

        issueA(0); issueA(1); issueA(2);

        for (int c = 0; c < 16; c++) {
            CP_WAIT2();
            __syncthreads();
            issueA(c + 3);

            const uint32_t ta = aring + (c & (LA_NSTG - 1)) * LA_STAGE;
            const uint32_t tbB = sbase + c * (64 * ROWB);
            #pragma unroll
            for (int kk = 0; kk < 2; kk++) {
                const uint32_t kba = kk * 32;
                uint32_t ah[4][4], al[4][4], bb[2][2];
                #pragma unroll
                for (int mi = 0; mi < 4; mi++) {
                    ldsm4(ah[mi], ta + 0 * BTILE + a_off + mi * 16 * ROWB + kba);
                    ldsm4(al[mi], ta + 1 * BTILE + a_off + mi * 16 * ROWB + kba);
                }
                {
                    uint32_t t4[4];
                    ldsm4(t4, tbB + b_off + kba);
                    bb[0][0] = t4[0]; bb[0][1] = t4[1]; bb[1][0] = t4[2]; bb[1][1] = t4[3];
                }
                #pragma unroll
                for (int mi = 0; mi < 4; mi++)
                    #pragma unroll
                    for (int ni = 0; ni < 2; ni++) {
                        mma16816(acc[mi][ni], ah[mi], bb[ni]);
                        mma16816(acc[mi][ni], al[mi], bb[ni]);
                    }
            }
        }

        __syncthreads();
        float* Gs = (float*)(smem + LB_ALL);
        #pragma unroll
        for (int mi = 0; mi < 4; mi++) {
            const int r0 = wm * 64 + mi * 16 + (lane >> 2);
            const int r1 = r0 + 8;
            #pragma unroll
            for (int ni = 0; ni < 2; ni++) {
                const int cl = wn * 16 + ni * 8 + (lane & 3) * 2;
                Gs[r0 * 68 + cl]     = acc[mi][ni][0];
                Gs[r0 * 68 + cl + 1] = acc[mi][ni][1];
                Gs[r1 * 68 + cl]     = acc[mi][ni][2];
                Gs[r1 * 68 + cl + 1] = acc[mi][ni][3];
            }
        }
        __syncthreads();

        for (int p = tid; p < 128 * 16; p += 256) {
            const int b = p >> 4, l = p & 15;
            const int hcol = h0 + l;
            const float* xg = g_xg + ((long)b * Tn + t) * 2048;
            float gi = Gs[b * 68 + 0 * 16 + l] + xg[0 * 512 + hcol];
            float gf = Gs[b * 68 + 1 * 16 + l] + xg[1 * 512 + hcol];
            float gg = Gs[b * 68 + 2 * 16 + l] + xg[2 * 512 + hcol];
            float go = Gs[b * 68 + 3 * 16 + l] + xg[3 * 512 + hcol];
            float co = g_c[b * 512 + hcol];
            float si = 1.f / (1.f + __expf(-gi));
            float sf = 1.f / (1.f + __expf(-gf));
            float so = 1.f / (1.f + __expf(-go));
            float cn = sf * co + si * tanhf(gg);
            float hn = so * tanhf(cn);
            g_c[b * 512 + hcol] = cn;
            split_write16(hn, g_hs_h, g_hs_l, ((long)b * Tn + t) * 512 + hcol);
        }

        __syncthreads();
        if (tid == 0) {
            __threadfence();
            atomicAdd(&g_bar, 1u);
            while (*(volatile unsigned*)&g_bar < 32u * (unsigned)t) { }
            __threadfence();
        }
        __syncthreads();
    }
}

__global__ void k_lstm_t0()
{
    int i = blockIdx.x * blockDim.x + threadIdx.x;
    if (i == 0) g_bar = 0u;
    if (i >= Bn * Hn) return;
    int b = i >> 9, hcol = i & 511;
    const float* xg = g_xg + ((long)b * Tn) * 2048;
    float gi = xg[hcol], gg = xg[1024 + hcol], go = xg[1536 + hcol];
    float si = 1.f / (1.f + __expf(-gi));
    float so = 1.f / (1.f + __expf(-go));
    float cn = si * tanhf(gg);
    float hn = so * tanhf(cn);
    g_c[i] = cn;
    split_write16(hn, g_hs_h, g_hs_l, ((long)b * Tn) * 512 + hcol);
}

// ===================== split-K fp32 GEMM for img =====================
__global__ __launch_bounds__(256)
void sgemm_splitk(const float* __restrict__ A, const float* __restrict__ Bw)
{
    __shared__ float As[16][64];
    __shared__ float Bs[16][64];
    const int tid = threadIdx.x;
    const int tx = tid & 15, ty = tid >> 4;
    const int n0 = blockIdx.x * 64, m0 = blockIdx.y * 64;
    const int kbase = blockIdx.z * 256;
    const int lr = tid >> 2, lk = (tid & 3) * 4;
    const float* Ap = A  + (long)(m0 + lr) * 2048 + kbase + lk;
    const float* Bp = Bw + (long)(n0 + lr) * 2048 + kbase + lk;

    float acc[4][4] = {};
    for (int k0 = 0; k0 < 256; k0 += 16) {
        float4 avv = *(const float4*)(Ap + k0);
        float4 bvv = *(const float4*)(Bp + k0);
        __syncthreads();
        As[lk+0][lr] = avv.x; As[lk+1][lr] = avv.y; As[lk+2][lr] = avv.z; As[lk+3][lr] = avv.w;
        Bs[lk+0][lr] = bvv.x; Bs[lk+1][lr] = bvv.y; Bs[lk+2][lr] = bvv.z; Bs[lk+3][lr] = bvv.w;
        __syncthreads();
        #pragma unroll
        for (int kk = 0; kk < 16; kk++) {
            float a[4], b[4];
            #pragma unroll
            for (int i = 0; i < 4; i++) a[i] = As[kk][ty * 4 + i];
            #pragma unroll
            for (int j = 0; j < 4; j++) b[j] = Bs[kk][tx * 4 + j];
            #pragma unroll
            for (int i = 0; i < 4; i++)
                #pragma unroll
                for (int j = 0; j < 4; j++) acc[i][j] += a[i] * b[j];
        }
    }
    float* Cp = g_part + (long)blockIdx.z * Bn * VISn;
    #pragma unroll
    for (int i = 0; i < 4; i++)
        #pragma unroll
        for (int j = 0; j < 4; j++)
            Cp[(long)(m0 + ty * 4 + i) * VISn + n0 + tx * 4 + j] = acc[i][j];
}

__global__ void k_img_reduce(const float* __restrict__ img_b) {
    int b = blockIdx.x, v = threadIdx.x;
    float s = img_b[v];
    #pragma unroll
    for (int k = 0; k < 8; k++) s += g_part[((long)k * Bn + b) * VISn + v];
    g_x16[(long)(b * Tn) * 1024 + v] = __float2half_rn(s);
}

// ===================== prep kernels =====================
__global__ void k_bias2(const float* __restrict__ b_ih, const float* __restrict__ b_hh) {
    int i = blockIdx.x * blockDim.x + threadIdx.x;
    if (i < 4 * Hn) g_bias2[i] = b_ih[i] + b_hh[i];
}
__global__ void k_cvt16(const float* __restrict__ x, __half* __restrict__ h, int n4) {
    int i = blockIdx.x * blockDim.x + threadIdx.x;
    if (i >= n4) return;
    float4 v = ((const float4*)x)[i];
    __half2 a = __floats2half2_rn(v.x, v.y);
    __half2 b = __floats2half2_rn(v.z, v.w);
    ((uint2*)h)[i] = make_uint2(*(uint32_t*)&a, *(uint32_t*)&b);
}
__global__ void k_transpose_f(const float* __restrict__ features) {
    int bp = blockIdx.x;
    int b = bp / 49, p = bp % 49;
    int v = threadIdx.x;
    g_fT[(long)bp * 512 + v] =
        __float2half_rn(features[((long)b * 512 + v) * 49 + p]);
}
__global__ void k_normalize() {
    int row = blockIdx.x;
    int b = row / 49, p = row % 49;
    const float* x = g_fv + (long)row * 512;
    __shared__ float red[8];
    int tid = threadIdx.x, lane = tid & 31, wid = tid >> 5;
    float s = 0.f;
    for (int v = tid; v < 512; v += 256) { float t = x[v]; s += t * t; }
    #pragma unroll
    for (int o = 16; o; o >>= 1) s += __shfl_xor_sync(0xffffffffu, s, o);
    if (lane == 0) red[wid] = s;
    __syncthreads();
    if (tid == 0) {
        float sum = 0.f;
        #pragma unroll
        for (int w = 0; w < 8; w++) sum += red[w];
        red[0] = 1.f / fmaxf(sqrtf(sum), 1e-12f);
    }
    __syncthreads();
    float inv = red[0];
    long o = ((long)b * 64 + p) * 512;
    for (int v = tid; v < 512; v += 256) {
        float val = x[v] * inv;
        g_features_all[o + v] = val;
        g_fall16[o + v] = __float2half_rn(val);
    }
}
__global__ void k_copy_eng(const float* __restrict__ eng) {
    int bj = blockIdx.x;
    int b = bj / 15, j = bj % 15;
    int v = threadIdx.x;
    float val = eng[(long)bj * 512 + v];
    long o = ((long)b * 64 + 49 + j) * 512 + v;
    g_features_all[o] = val;
    g_fall16[o] = __float2half_rn(val);
}
__global__ void k_embed(const int* __restrict__ captions, const float* __restrict__ embed_w) {
    int r = blockIdx.x;
    int idx = captions[r];
    float v = embed_w[(long)idx * 512 + threadIdx.x];
    __half hv = __float2half_rn(v);
    g_we16[(long)r * 512 + threadIdx.x] = hv;
    g_x16[(long)r * 1024 + 512 + threadIdx.x] = hv;
}

// ===================== attention: scores =====================
__global__ __launch_bounds__(256)
void k_att_scores(const float* __restrict__ att_bias, const float* __restrict__ att_w) {
    const int n0 = blockIdx.x * 8, b = blockIdx.y;
    __shared__ float fea8[8][512];
    __shared__ float ws[512];
    __shared__ float hh[512];
    const int tid = threadIdx.x, lane = tid & 31, wid = tid >> 5;

    for (int v = tid; v < 512; v += 256) ws[v] = att_w[v];
    const float4* fea = (const float4*)(g_att_fea + ((long)b * 64 + n0) * 512);
    for (int i = tid; i < 8 * 128; i += 256)
        ((float4*)&fea8[0][0])[i] = fea[i];
    const float bn = att_bias[n0 + wid];

    for (int t = 0; t < Tn - 1; t++) {
        __syncthreads();
        for (int v = tid; v < 512; v += 256) hh[v] = g_att_h[((long)b * Tn + t) * 512 + v];
        __syncthreads();
        float s = 0.f;
        #pragma unroll 4
        for (int v = lane; v < 512; v += 32)
            s += fmaxf(fea8[wid][v] + hh[v] + bn, 0.f) * ws[v];
        #pragma unroll
        for (int o = 16; o; o >>= 1) s += __shfl_xor_sync(0xffffffffu, s, o);
        if (lane == 0) g_scores[((long)b * (Tn - 1) + t) * 64 + n0 + wid] = s;
    }
}

// ===================== attention: softmax + context =====================
#define CTX_SMEM (64 * 512 * 4 + 256)
__global__ __launch_bounds__(512)
void k_att_ctx() {
    extern __shared__ float fs[];
    float* sout = fs + 64 * 512;
    const int b = blockIdx.x, tid = threadIdx.x, lane = tid & 31, wid = tid >> 5;

    const float4* src = (const float4*)(g_features_all + (long)b * 64 * 512);
    for (int i = tid; i < 64 * 128; i += 512) ((float4*)fs)[i] = src[i];
    __syncthreads();

    for (int t = 0; t < Tn - 1; t++) {
        if (wid == 0) {
            const float* sc = g_scores + ((long)b * (Tn - 1) + t) * 64;
            float s0 = sc[lane], s1 = sc[lane + 32];
            float m = fmaxf(s0, s1);
            #pragma unroll
            for (int o = 16; o; o >>= 1) m = fmaxf(m, __shfl_xor_sync(0xffffffffu, m, o));
            float e0 = __expf(s0 - m), e1 = __expf(s1 - m);
            float sum = e0 + e1;
            #pragma unroll
            for (int o = 16; o; o >>= 1) sum += __shfl_xor_sync(0xffffffffu, sum, o);
            float inv = 1.f / sum;
            sout[lane] = e0 * inv; sout[lane + 32] = e1 * inv;
        }
        __syncthreads();
        float acc = 0.f;
        #pragma unroll 8
        for (int n = 0; n < 64; n++) acc += sout[n] * fs[n * 512 + tid];
        g_x16[((long)b * Tn + (t + 1)) * 1024 + tid] = __float2half_rn(acc);
        __syncthreads();
    }
}

// ===================== launch =====================
static inline dim3 tgrid256(int M, int N) { return dim3((N + 255) / 256, (M + 63) / 64); }

extern "C" void kernel_launch(void* const* d_in, const int* in_sizes, int n_in,
                              void* d_out, int out_size)
{
    const float* feature_0 = (const float*)d_in[0];
    const float* features  = (const float*)d_in[1];
    const float* eng       = (const float*)d_in[2];
    const int*   captions  = (const int*)  d_in[3];
    const int*   lengths   = (const int*)  d_in[4];
    const float* embed_w   = (const float*)d_in[5];
    const float* w_ih      = (const float*)d_in[6];
    const float* w_hh      = (const float*)d_in[7];
    const float* b_ih      = (const float*)d_in[8];
    const float* b_hh      = (const float*)d_in[9];
    const float* fc_w      = (const float*)d_in[10];
    const float* fc_b      = (const float*)d_in[11];
    const float* att_vw_w  = (const float*)d_in[12];
    const float* att_hw_w  = (const float*)d_in[13];
    const float* att_bias  = (const float*)d_in[14];
    const float* att_w_w   = (const float*)d_in[15];
    const float* att_fc_w  = (const float*)d_in[16];
    const float* att_fc_b  = (const float*)d_in[17];
    const float* img_w     = (const float*)d_in[18];
    const float* img_b     = (const float*)d_in[19];
    float* out = (float*)d_out;

    static bool init_done = false;
    static cudaStream_t s1;
    static cudaEvent_t ev0, ev1, ev3, evEnd, evL1, evFcA;
    if (!init_done) {
        cudaFuncSetAttribute(mma_gemm1,   cudaFuncAttributeMaxDynamicSharedMemorySize, S2_SMEM);
        cudaFuncSetAttribute(mma_gemm_fc, cudaFuncAttributeMaxDynamicSharedMemorySize, S2_SMEM);
        cudaFuncSetAttribute(k_lstm_all,  cudaFuncAttributeMaxDynamicSharedMemorySize, LP_SMEM);
        cudaFuncSetAttribute(k_att_ctx,   cudaFuncAttributeMaxDynamicSharedMemorySize, CTX_SMEM);
        cudaStreamCreateWithFlags(&s1, cudaStreamNonBlocking);
        cudaEventCreateWithFlags(&ev0,   cudaEventDisableTiming);
        cudaEventCreateWithFlags(&ev1,   cudaEventDisableTiming);
        cudaEventCreateWithFlags(&ev3,   cudaEventDisableTiming);
        cudaEventCreateWithFlags(&evEnd, cudaEventDisableTiming);
        cudaEventCreateWithFlags(&evL1,  cudaEventDisableTiming);
        cudaEventCreateWithFlags(&evFcA, cudaEventDisableTiming);
        init_done = true;
    }

    float* p_fv = nullptr;    cudaGetSymbolAddress((void**)&p_fv,    g_fv);
    float* p_ah = nullptr;    cudaGetSymbolAddress((void**)&p_ah,    g_att_h);
    float* p_xg = nullptr;    cudaGetSymbolAddress((void**)&p_xg,    g_xg);
    float* p_bias2 = nullptr; cudaGetSymbolAddress((void**)&p_bias2, g_bias2);
    float* p_afea = nullptr;  cudaGetSymbolAddress((void**)&p_afea,  g_att_fea);
    int* p_rmA = nullptr;     cudaGetSymbolAddress((void**)&p_rmA,   g_rowmapA);
    int* p_rmB = nullptr;     cudaGetSymbolAddress((void**)&p_rmB,   g_rowmapB);
    int* p_nkA = nullptr;     cudaGetSymbolAddress((void**)&p_nkA,   g_nkA);
    int* p_nkB = nullptr;     cudaGetSymbolAddress((void**)&p_nkB,   g_nkB);
    #define HSYM(p, s) __half* p = nullptr; cudaGetSymbolAddress((void**)&p, s)
    HSYM(p_fT, g_fT);
    HSYM(p_fall16, g_fall16);
    HSYM(p_we16, g_we16);
    HSYM(p_x16, g_x16);
    HSYM(p_hs_h, g_hs_h);
    HSYM(p_wfc1, g_wfc1);     HSYM(p_wvw, g_wvw);
    HSYM(p_whw, g_whw);       HSYM(p_wih, g_wih);
    HSYM(p_wfc, g_wfc);       HSYM(p_whh, g_whh);
    #undef HSYM

    // ---- fork: side stream s1 handles all off-critical-path work ----
    cudaEventRecord(ev0, 0);
    cudaStreamWaitEvent(s1, ev0, 0);

    // side stream: early deps for att_fea/scores
    k_cvt16<<<(512 * 512 / 4 + 255) / 256, 256, 0, s1>>>(att_vw_w, p_wvw, 512 * 512 / 4);
    k_copy_eng<<<Bn * 15, 512, 0, s1>>>(eng);
    k_embed<<<Bn * Tn, 512, 0, s1>>>(captions, embed_w);
    k_cvt16<<<(512 * 512 / 4 + 255) / 256, 256, 0, s1>>>(att_hw_w, p_whw, 512 * 512 / 4);
    mma_gemm1<<<tgrid256(Bn * Tn, 512), 256, S2_SMEM, s1>>>(p_we16, p_whw,
        p_ah, 512, nullptr, 512, 512);                       // att_h
    cudaEventRecord(ev1, s1);

    // side stream: deps for xg / LSTM
    k_cvt16<<<(2048 * 1024 / 4 + 255) / 256, 256, 0, s1>>>(w_ih, p_wih, 2048 * 1024 / 4);
    sgemm_splitk<<<dim3(8, 2, 8), 256, 0, s1>>>(feature_0, img_w);
    k_img_reduce<<<Bn, 512, 0, s1>>>(img_b);
    k_bias2<<<(4 * Hn + 255) / 256, 256, 0, s1>>>(b_ih, b_hh);
    k_cvt16<<<(2048 * 512 / 4 + 255) / 256, 256, 0, s1>>>(w_hh, p_whh, 2048 * 512 / 4);
    cudaEventRecord(ev3, s1);

    // side stream: deps for fc
    k_cvt16<<<(Vn * 512 / 4 + 255) / 256, 256, 0, s1>>>(fc_w, p_wfc, Vn * 512 / 4);
    k_rowmap<<<1, 256, 0, s1>>>(lengths);
    k_zero_masked<<<Bn * Tn, 256, 0, s1>>>(lengths, out);
    cudaEventRecord(evEnd, s1);

    // ---- main stream: critical chain ----
    k_cvt16<<<(512 * 512 / 4 + 255) / 256, 256>>>(att_fc_w, p_wfc1, 512 * 512 / 4);
    k_transpose_f<<<Bn * 49, 512>>>(features);

    // att_fc: fv = fT @ att_fc_w.T + b
    mma_gemm1<<<tgrid256(Bn * 49, 512), 256, S2_SMEM>>>(p_fT, p_wfc1,
        p_fv, 512, att_fc_b, 512, 512);
    k_normalize<<<Bn * 49, 256>>>();

    cudaStreamWaitEvent(0, ev1, 0);   // wvw, copy_eng, att_h ready

    // att_fea = features_all @ att_vw_w.T
    mma_gemm1<<<tgrid256(Bn * 64, 512), 256, S2_SMEM>>>(p_fall16, p_wvw,
        p_afea, 512, nullptr, 512, 512);

    // attention: scores then softmax+context -> g_x16 rows t=1..19
    k_att_scores<<<dim3(8, Bn), 256>>>(att_bias, att_w_w);
    k_att_ctx<<<Bn, 512, CTX_SMEM>>>();

    cudaStreamWaitEvent(0, ev3, 0);   // wih, img, bias2, whh ready

    // xg = [feas|we] @ w_ih.T + (b_ih+b_hh)
    mma_gemm1<<<tgrid256(Bn * Tn, 4 * Hn), 256, S2_SMEM>>>(p_x16, p_wih,
        p_xg, 4 * Hn, p_bias2, 4 * Hn, 1024);

    // LSTM part 1 (steps 1..9)
    k_lstm_t0<<<(Bn * Hn + 255) / 256, 256>>>();
    k_lstm_all<<<32, 256, LP_SMEM>>>(1, 10);
    cudaEventRecord(evL1, 0);

    // side stream: fcA (rows t<=9) overlaps LSTM part 2 + fcB
    cudaStreamWaitEvent(s1, evL1, 0);   // hs rows t<=9 ready (wfc/rowmap/zero by s1 order)
    mma_gemm_fc<<<tgrid256(128 * 10, Vn), 256, S2_SMEM, s1>>>(p_hs_h, p_wfc,
        out, Vn, fc_b, Vn, 512, p_rmA, p_nkA);
    cudaEventRecord(evFcA, s1);

    // main: LSTM part 2 (steps 10..19), then fcB (rows t>=10)
    k_lstm_all<<<32, 256, LP_SMEM>>>(10, 20);
    cudaStreamWaitEvent(0, evEnd, 0);   // wfc, rowmap, zero_masked done
    mma_gemm_fc<<<tgrid256(128 * 10, Vn), 256, S2_SMEM>>>(p_hs_h, p_wfc,
        out, Vn, fc_b, Vn, 512, p_rmB, p_nkB);

    // join side branch (fcA) before capture end
    cudaStreamWaitEvent(0, evFcA, 0);
}